// round 17
// baseline (speedup 1.0000x reference)
#include <cuda_runtime.h>
#include <cuda_fp16.h>

#define BB 2
#define TT 2048
#define DD 1024
#define HH 16
#define DH 64
#define MROWS (BB*TT)
#define KQV_LD (3*DD)
#define NCHUNK 32          // 2048 / 64

// fp16 operands + scratch (device globals; allocation is forbidden)
__device__ __half g_xh [(size_t)MROWS*DD];
__device__ __half g_w1h[(size_t)DD*3*DD];   // natural [K][N]
__device__ __half g_w2h[(size_t)DD*DD];
__device__ __half g_kqvh[(size_t)MROWS*3*DD];
__device__ __half g_aoh[(size_t)MROWS*DD];
__device__ float  g_C  [(size_t)BB*HH*NCHUNK*DH*DH];   // per-chunk K^T V (fp32)
__device__ __half g_ph [(size_t)BB*HH*NCHUNK*DH*DH];   // exclusive prefix (fp16)

// ---------------------------------------------------------------------------
// helpers
// ---------------------------------------------------------------------------
__device__ __forceinline__ unsigned h2_pack(__half a, __half b) {
    __half2 t = __halves2half2(a, b);
    return *reinterpret_cast<unsigned*>(&t);
}
__device__ __forceinline__ unsigned hpack2(float x, float y) {
    return h2_pack(__float2half_rn(x), __float2half_rn(y));
}
__device__ __forceinline__ void mma16816(float* c,
    unsigned a0, unsigned a1, unsigned a2, unsigned a3,
    unsigned b0, unsigned b1)
{
    asm volatile(
        "mma.sync.aligned.m16n8k16.row.col.f32.f16.f16.f32 "
        "{%0,%1,%2,%3},{%4,%5,%6,%7},{%8,%9},{%0,%1,%2,%3};\n"
        : "+f"(c[0]), "+f"(c[1]), "+f"(c[2]), "+f"(c[3])
        : "r"(a0), "r"(a1), "r"(a2), "r"(a3), "r"(b0), "r"(b1));
}
__device__ __forceinline__ void ldsm4(unsigned* r, const void* p) {
    unsigned a = (unsigned)__cvta_generic_to_shared(p);
    asm volatile("ldmatrix.sync.aligned.m8n8.x4.shared.b16 {%0,%1,%2,%3}, [%4];\n"
        : "=r"(r[0]), "=r"(r[1]), "=r"(r[2]), "=r"(r[3]) : "r"(a));
}
__device__ __forceinline__ void ldsm4t(unsigned* r, const void* p) {
    unsigned a = (unsigned)__cvta_generic_to_shared(p);
    asm volatile("ldmatrix.sync.aligned.m8n8.x4.trans.shared.b16 {%0,%1,%2,%3}, [%4];\n"
        : "=r"(r[0]), "=r"(r[1]), "=r"(r[2]), "=r"(r[3]) : "r"(a));
}
__device__ __forceinline__ void cp16(void* sp, const void* gp) {
    unsigned s = (unsigned)__cvta_generic_to_shared(sp);
    asm volatile("cp.async.cg.shared.global [%0], [%1], 16;\n" :: "r"(s), "l"(gp));
}
#define CP_COMMIT() asm volatile("cp.async.commit_group;\n")
#define CP_WAIT(n)  asm volatile("cp.async.wait_group %0;\n" :: "n"(n))

// ---------------------------------------------------------------------------
// prep: one kernel converts x, W1, W2 -> fp16
// ---------------------------------------------------------------------------
#define NX4  (MROWS*DD/4)
#define NW14 (DD*3*DD/4)
#define NW24 (DD*DD/4)
__global__ void prep_all(const float* __restrict__ x,
                         const float* __restrict__ W1,
                         const float* __restrict__ W2,
                         __half* __restrict__ xh,
                         __half* __restrict__ w1h,
                         __half* __restrict__ w2h)
{
    int i = blockIdx.x * blockDim.x + threadIdx.x;
    const float* src; __half* dst; int off;
    if (i < NX4)                   { src = x;  dst = xh;  off = i; }
    else if (i < NX4 + NW14)       { src = W1; dst = w1h; off = i - NX4; }
    else if (i < NX4 + NW14 + NW24){ src = W2; dst = w2h; off = i - NX4 - NW14; }
    else return;
    float4 v = reinterpret_cast<const float4*>(src)[off];
    reinterpret_cast<uint2*>(dst)[off] = make_uint2(hpack2(v.x, v.y), hpack2(v.z, v.w));
}

// ---------------------------------------------------------------------------
// fp16 single-product GEMM (unchanged, proven R11/R12)
// ---------------------------------------------------------------------------
#define APG 72
#define BPG 136
#define SA_ST (128*APG)
#define SB_ST (64*BPG)
#define NSG 3
#define GEMM_SMEM ((NSG*SA_ST + NSG*SB_ST) * 2)

#define GEMM_LOAD(s, k0)                                                        \
    {                                                                           \
        _Pragma("unroll")                                                       \
        for (int j = 0; j < 8; j++) {                                           \
            const int id = tid + 128 * j;                                       \
            const int arow = id >> 3, ac = (id & 7) * 8;                        \
            const size_t ga = (size_t)(m0 + arow) * K + (k0) + ac;              \
            cp16(sA + (s)*SA_ST + arow*APG + ac, Ah_g + ga);                    \
            const int brow = id >> 4, bc = (id & 15) * 8;                       \
            const size_t gb = (size_t)((k0) + brow) * N + n0 + bc;              \
            cp16(sB + (s)*SB_ST + brow*BPG + bc, Bh_g + gb);                    \
        }                                                                       \
        CP_COMMIT();                                                            \
    }

template<int OMODE>
__global__ __launch_bounds__(128, 2) void gemm_h(
    const __half* __restrict__ Ah_g,
    const __half* __restrict__ Bh_g,
    const float* __restrict__ bias,
    float* __restrict__ C, __half* __restrict__ Ch,
    int M, int N, int K)
{
    extern __shared__ __half smg[];
    __half* sA = smg;
    __half* sB = smg + NSG*SA_ST;

    const int tid = threadIdx.x, warp = tid >> 5, lane = tid & 31;
    const int m0 = blockIdx.y * 128, n0 = blockIdx.x * 128;
    const int wm = (warp & 1) * 64, wn = (warp >> 1) * 64;

    float acc[4][8][4];
#pragma unroll
    for (int i = 0; i < 4; i++)
#pragma unroll
        for (int j = 0; j < 8; j++)
#pragma unroll
            for (int l = 0; l < 4; l++) acc[i][j][l] = 0.f;

    GEMM_LOAD(0, 0);
    GEMM_LOAD(1, 64);

    const int brr = (lane & 8) + (lane & 7);
    const int bcsel = (lane >> 1) & 8;
    const int arr = (lane & 15), akk = ((lane & 16) >> 1);

    const int ntiles = K / 64;
    for (int t = 0; t < ntiles; t++) {
        if (t + 1 < ntiles) { CP_WAIT(1); } else { CP_WAIT(0); }
        __syncthreads();
        if (t + 2 < ntiles) GEMM_LOAD((t + 2) % NSG, (t + 2) * 64);

        const int s = t % NSG;
        const __half* Ahs = sA + s*SA_ST;
        const __half* Bhs = sB + s*SB_ST;

        unsigned bb[2][4][4], aa[2][4];
#pragma unroll
        for (int np = 0; np < 4; np++)
            ldsm4t(bb[0][np], Bhs + brr * BPG + wn + np * 16 + bcsel);

#pragma unroll
        for (int ki = 0; ki < 4; ki++) {
            const int ks = ki * 16;
            if (ki < 3) {
#pragma unroll
                for (int np = 0; np < 4; np++)
                    ldsm4t(bb[(ki + 1) & 1][np], Bhs + (ks + 16 + brr) * BPG + wn + np * 16 + bcsel);
            }
            ldsm4(aa[0], Ahs + (wm + arr) * APG + ks + akk);
#pragma unroll
            for (int mt = 0; mt < 4; mt++) {
                if (mt < 3)
                    ldsm4(aa[(mt + 1) & 1], Ahs + (wm + (mt + 1) * 16 + arr) * APG + ks + akk);
                const unsigned* a = aa[mt & 1];
#pragma unroll
                for (int nt = 0; nt < 8; nt++) {
                    mma16816(acc[mt][nt], a[0], a[1], a[2], a[3],
                             bb[ki & 1][nt >> 1][(nt & 1) * 2],
                             bb[ki & 1][nt >> 1][(nt & 1) * 2 + 1]);
                }
            }
        }
    }

    const int g = lane >> 2, tg = lane & 3;
#pragma unroll
    for (int mt = 0; mt < 4; mt++) {
        const int r = m0 + wm + mt * 16 + g;
#pragma unroll
        for (int nt = 0; nt < 8; nt++) {
            const int c = n0 + wn + nt * 8 + tg * 2;
            const float bx = bias[c], by = bias[c + 1];
            const float v0 = acc[mt][nt][0] + bx, v1 = acc[mt][nt][1] + by;
            const float v2 = acc[mt][nt][2] + bx, v3 = acc[mt][nt][3] + by;
            if (OMODE == 1) {
                *reinterpret_cast<unsigned*>(&Ch[(size_t)r * N + c])       = hpack2(v0, v1);
                *reinterpret_cast<unsigned*>(&Ch[(size_t)(r + 8) * N + c]) = hpack2(v2, v3);
            } else {
                float2 o0 = {v0, v1}, o1 = {v2, v3};
                *reinterpret_cast<float2*>(&C[(size_t)r * N + c])       = o0;
                *reinterpret_cast<float2*>(&C[(size_t)(r + 8) * N + c]) = o1;
            }
        }
    }
}

// ---------------------------------------------------------------------------
// Kernel A: per-(b,h,chunk) outer-product sum  C_c = K_c^T V_c  (64x64 fp32)
// ---------------------------------------------------------------------------
#define AP 72
__global__ __launch_bounds__(128, 4) void kv_outer(
    const __half* __restrict__ kqvh, float* __restrict__ Cc)
{
    __shared__ __half Ks[64*AP], Vs[64*AP];

    const int tid = threadIdx.x, warp = tid >> 5, lane = tid & 31;
    const int chunk = blockIdx.x, h = blockIdx.y, b = blockIdx.z;
    const int k0 = chunk * 64;

    const size_t hoff = (size_t)b * TT * KQV_LD + h * DH;
    const __half *Khg = kqvh + hoff;
    const __half *Vhg = Khg + 2*DD;

#pragma unroll
    for (int j = 0; j < 4; j++) {
        const int id = tid + 128 * j;
        const int row = id >> 3, c8 = (id & 7) * 8;
        const size_t gk = (size_t)(k0 + row) * KQV_LD + c8;
        cp16(Ks + row * AP + c8, Khg + gk);
        cp16(Vs + row * AP + c8, Vhg + gk);
    }
    CP_COMMIT();
    CP_WAIT(0);
    __syncthreads();

    const int m = warp * 16;
    const int vrr = (lane & 8) + (lane & 7);
    const int vcc = (lane >> 1) & 8;
    const int arow = ((lane & 16) >> 1) + (lane & 7);
    const int acol = lane & 8;

    float cacc[8][4];
#pragma unroll
    for (int j = 0; j < 8; j++)
#pragma unroll
        for (int l = 0; l < 4; l++) cacc[j][l] = 0.f;

#pragma unroll
    for (int ks = 0; ks < 64; ks += 16) {
        unsigned af[4];
        ldsm4t(af, Ks + (ks + arow) * AP + m + acol);
        unsigned vf[4][4];
#pragma unroll
        for (int np = 0; np < 4; np++)
            ldsm4t(vf[np], Vs + (ks + vrr) * AP + np * 16 + vcc);
#pragma unroll
        for (int nt = 0; nt < 8; nt++)
            mma16816(cacc[nt], af[0], af[1], af[2], af[3],
                     vf[nt >> 1][(nt & 1) * 2], vf[nt >> 1][(nt & 1) * 2 + 1]);
    }

    const int g = lane >> 2, tg = lane & 3;
    const size_t cbase = ((size_t)(b * HH + h) * NCHUNK + chunk) * (DH * DH);
#pragma unroll
    for (int nt = 0; nt < 8; nt++) {
        const int col = nt * 8 + tg * 2;
        const int r0 = m + g;
        float2 o0 = {cacc[nt][0], cacc[nt][1]};
        float2 o1 = {cacc[nt][2], cacc[nt][3]};
        *reinterpret_cast<float2*>(&Cc[cbase + (size_t)r0 * 64 + col])       = o0;
        *reinterpret_cast<float2*>(&Cc[cbase + (size_t)(r0 + 8) * 64 + col]) = o1;
    }
}

// ---------------------------------------------------------------------------
// Kernel B: exclusive prefix over chunks -> fp16.
// smem-staged: block (bh, 256-elem slice) loads all 32 chunk rows with full
// MLP (independent coalesced loads), then scans from smem (no DRAM chain).
// grid (32, 16), 256 thr, 32 KB smem.
// ---------------------------------------------------------------------------
#define EC (DH*DH)      // 4096 elements per chunk matrix
#define PSEL 256        // elements per block slice
__global__ __launch_bounds__(256) void prefix_split(
    const float* __restrict__ Cc, __half* __restrict__ ph)
{
    __shared__ float sm[NCHUNK * PSEL];   // 32 KB

    const int bh = blockIdx.x;                      // 0..31
    const int e0 = blockIdx.y * PSEL;               // slice base
    const int tid = threadIdx.x;                    // 0..255
    const size_t base = (size_t)bh * NCHUNK * EC + e0 + tid;

    // phase 1: fully parallel coalesced loads (MLP = 32)
#pragma unroll
    for (int c = 0; c < NCHUNK; c++)
        sm[c * PSEL + tid] = Cc[base + (size_t)c * EC];
    __syncthreads();

    // phase 2: serial scan from smem (latency-free), coalesced fp16 stores
    float run = 0.f;
#pragma unroll
    for (int c = 0; c < NCHUNK; c++) {
        ph[base + (size_t)c * EC] = __float2half_rn(run);
        run += sm[c * PSEL + tid];
    }
}

// ---------------------------------------------------------------------------
// Kernel C: per-(b,h,chunk)  O_c = Q_c P_prev + tril(Q_c K_c^T) V_c
// 4 warps, warp w owns q rows [16w, 16w+16) x all 64 d. P hi-only.
// ---------------------------------------------------------------------------
#define ATTC_SMEM (4 * 64 * AP * 2)   // Qs,Ks,Vs,Ph = 36864 B

__global__ __launch_bounds__(128, 3) void attn_chunk(
    const __half* __restrict__ kqvh,
    const __half* __restrict__ ph,
    __half* __restrict__ aoh)
{
    extern __shared__ __half smc[];
    __half *Qs = smc;
    __half *Ks = Qs + 64*AP;
    __half *Vs = Ks + 64*AP;
    __half *Ph = Vs + 64*AP;

    const int tid = threadIdx.x, warp = tid >> 5, lane = tid & 31;
    const int chunk = blockIdx.x, h = blockIdx.y, b = blockIdx.z;
    const int q0 = chunk * 64;
    const int bh = b * HH + h;

    const size_t hoff = (size_t)b * TT * KQV_LD + h * DH;
    const __half *Khg = kqvh + hoff;
    const __half *Qhg = Khg + DD;
    const __half *Vhg = Khg + 2*DD;
    const size_t pbase = ((size_t)bh * NCHUNK + chunk) * (DH*DH);

#pragma unroll
    for (int j = 0; j < 4; j++) {
        const int id = tid + 128 * j;
        const int row = id >> 3, c8 = (id & 7) * 8;
        const size_t gk = (size_t)(q0 + row) * KQV_LD + c8;
        const int d = row * AP + c8;
        cp16(Qs + d, Qhg + gk);
        cp16(Ks + d, Khg + gk);
        cp16(Vs + d, Vhg + gk);
        cp16(Ph + d, ph + pbase + (size_t)row * 64 + c8);
    }
    CP_COMMIT();
    CP_WAIT(0);
    __syncthreads();

    const int wq = warp * 16;
    const int g = lane >> 2, tg = lane & 3;
    const int vrr = (lane & 8) + (lane & 7);
    const int vcc = (lane >> 1) & 8;
    const int krr = (lane >> 1) & 8;
    const int kdd = lane & 8;

    // Q fragments (A-operand, row-major)
    unsigned qf[4][4];
#pragma unroll
    for (int dsi = 0; dsi < 4; dsi++)
        ldsm4(qf[dsi], Qs + (wq + (lane & 15)) * AP + dsi * 16 + ((lane & 16) >> 1));

    float oacc[8][4];
#pragma unroll
    for (int j = 0; j < 8; j++)
#pragma unroll
        for (int l = 0; l < 4; l++) oacc[j][l] = 0.f;

    // ---- O = Q * P_prev (hi-only) ----
#pragma unroll
    for (int dsi = 0; dsi < 4; dsi++) {
        const int ds = dsi * 16;
        unsigned phf[4][4];
#pragma unroll
        for (int np = 0; np < 4; np++)
            ldsm4t(phf[np], Ph + (ds + vrr) * AP + np * 16 + vcc);
#pragma unroll
        for (int nt = 0; nt < 8; nt++)
            mma16816(oacc[nt], qf[dsi][0], qf[dsi][1], qf[dsi][2], qf[dsi][3],
                     phf[nt >> 1][(nt & 1) * 2], phf[nt >> 1][(nt & 1) * 2 + 1]);
    }

    // ---- S = Q K^T (intra-chunk) ----
    float sacc[8][4];
#pragma unroll
    for (int j = 0; j < 8; j++)
#pragma unroll
        for (int l = 0; l < 4; l++) sacc[j][l] = 0.f;

#pragma unroll
    for (int dsi = 0; dsi < 4; dsi++) {
        const int ds = dsi * 16;
        unsigned kf[4][4];
#pragma unroll
        for (int np = 0; np < 4; np++)
            ldsm4(kf[np], Ks + (np * 16 + krr + (lane & 7)) * AP + ds + kdd);
#pragma unroll
        for (int nt = 0; nt < 8; nt++)
            mma16816(sacc[nt], qf[dsi][0], qf[dsi][1], qf[dsi][2], qf[dsi][3],
                     kf[nt >> 1][(nt & 1) * 2], kf[nt >> 1][(nt & 1) * 2 + 1]);
    }

    // mask (local tril) + pack to A-fragments
    const int qr0 = wq + g, qr8 = qr0 + 8;
    unsigned aS[4][4];
#pragma unroll
    for (int nt = 0; nt < 8; nt++) {
        const int kc = nt * 8 + tg * 2;
        float s0 = sacc[nt][0], s1 = sacc[nt][1];
        float s2 = sacc[nt][2], s3 = sacc[nt][3];
        if (kc     > qr0) s0 = 0.f;
        if (kc + 1 > qr0) s1 = 0.f;
        if (kc     > qr8) s2 = 0.f;
        if (kc + 1 > qr8) s3 = 0.f;
        aS[nt >> 1][(nt & 1) * 2 + 0] = hpack2(s0, s1);
        aS[nt >> 1][(nt & 1) * 2 + 1] = hpack2(s2, s3);
    }

    // ---- O += S V (intra) ----
#pragma unroll
    for (int kc4 = 0; kc4 < 4; kc4++) {
        const int ks = kc4 * 16;
        unsigned vf[4][4];
#pragma unroll
        for (int np = 0; np < 4; np++)
            ldsm4t(vf[np], Vs + (ks + vrr) * AP + np * 16 + vcc);
#pragma unroll
        for (int nt = 0; nt < 8; nt++)
            mma16816(oacc[nt], aS[kc4][0], aS[kc4][1], aS[kc4][2], aS[kc4][3],
                     vf[nt >> 1][(nt & 1) * 2], vf[nt >> 1][(nt & 1) * 2 + 1]);
    }

    // write O (fp16)
    const size_t t = (size_t)b * TT + q0 + wq + g;
#pragma unroll
    for (int nt = 0; nt < 8; nt++) {
        const int c = h * DH + nt * 8 + tg * 2;
        *reinterpret_cast<unsigned*>(&aoh[t * DD + c])       = hpack2(oacc[nt][0], oacc[nt][1]);
        *reinterpret_cast<unsigned*>(&aoh[(t + 8) * DD + c]) = hpack2(oacc[nt][2], oacc[nt][3]);
    }
}

// ---------------------------------------------------------------------------
extern "C" void kernel_launch(void* const* d_in, const int* in_sizes, int n_in,
                              void* d_out, int out_size)
{
    const float* x  = (const float*)d_in[0];
    const float* W1 = (const float*)d_in[1];
    const float* b1 = (const float*)d_in[2];
    const float* W2 = (const float*)d_in[3];
    const float* b2 = (const float*)d_in[4];
    float* out = (float*)d_out;

    __half *xh, *w1h, *w2h, *kqvh, *aoh, *ph;
    float* Cc;
    cudaGetSymbolAddress((void**)&xh,  g_xh);
    cudaGetSymbolAddress((void**)&w1h, g_w1h);
    cudaGetSymbolAddress((void**)&w2h, g_w2h);
    cudaGetSymbolAddress((void**)&kqvh, g_kqvh);
    cudaGetSymbolAddress((void**)&aoh, g_aoh);
    cudaGetSymbolAddress((void**)&Cc,  g_C);
    cudaGetSymbolAddress((void**)&ph,  g_ph);

    cudaFuncSetAttribute(gemm_h<1>,
                         cudaFuncAttributeMaxDynamicSharedMemorySize, GEMM_SMEM);
    cudaFuncSetAttribute(gemm_h<0>,
                         cudaFuncAttributeMaxDynamicSharedMemorySize, GEMM_SMEM);
    cudaFuncSetAttribute(attn_chunk,
                         cudaFuncAttributeMaxDynamicSharedMemorySize, ATTC_SMEM);

    // 0) x/W1/W2 -> fp16 (single fused launch)
    {
        const int total = NX4 + NW14 + NW24;
        prep_all<<<(total + 255) / 256, 256>>>(x, W1, W2, xh, w1h, w2h);
    }
    // 1) kqv = x @ W1 + b1  (fp16 output)
    {
        dim3 grid(3 * DD / 128, MROWS / 128);
        gemm_h<1><<<grid, 128, GEMM_SMEM>>>(xh, w1h, b1, nullptr, kqvh,
                                            MROWS, 3 * DD, DD);
    }
    // 2a) per-chunk outer products C_c = K_c^T V_c
    {
        dim3 grid(NCHUNK, HH, BB);
        kv_outer<<<grid, 128>>>(kqvh, Cc);
    }
    // 2b) exclusive prefix over chunks (smem-staged scan)
    {
        dim3 grid(BB * HH, EC / PSEL);
        prefix_split<<<grid, 256>>>(Cc, ph);
    }
    // 2c) O_c = Q_c P_prev + tril(Q_c K_c^T) V_c
    {
        dim3 grid(NCHUNK, HH, BB);
        attn_chunk<<<grid, 128, ATTC_SMEM>>>(kqvh, ph, aoh);
    }
    // 3) out = ao @ W2 + b2  (fp32 output)
    {
        dim3 grid(DD / 128, MROWS / 128);
        gemm_h<0><<<grid, 128, GEMM_SMEM>>>(aoh, w2h, b2, out, nullptr,
                                            MROWS, DD, DD);
    }
}